// round 11
// baseline (speedup 1.0000x reference)
#include <cuda_runtime.h>
#include <cstdint>
#include <math.h>

#define Bb 8
#define Nn 4096
#define Cc 512
#define Kk 150
#define MROWS (Bb*Nn)
#define QCW 512          // qcat/kcat row width (3 x 160 + pad to 512)

// ---------------- scratch (device globals; no allocation allowed) -----------
__device__ float g_Xcat[(size_t)MROWS*1536]; // [x_hi | x_hi | x_lo] (tf32)
__device__ float g_Wcat[(size_t)300*1536];   // Wq,Wk rows; [hi|lo|hi] (tf32)
__device__ float g_bqk [512];
__device__ float g_Qcat[(size_t)MROWS*QCW];  // [hi|hi|lo] (tf32)
__device__ float g_Kcat[(size_t)MROWS*QCW];  // [hi|lo|hi] (tf32)
__device__ float g_Vt  [(size_t)Cc*MROWS];   // v^T (512, 32768), tf32-rounded
__device__ float g_S   [(size_t)Bb*Nn*Nn];   // raw scores fp32
__device__ float g_O   [(size_t)Bb*Nn*Cc];   // attn out, tf32-rounded
__device__ float g_Rmax[(size_t)MROWS];
__device__ float g_Rinv[(size_t)MROWS];

// ---------------- helpers ----------------------------------------------------
__device__ __forceinline__ uint32_t f2tf(float v) {
    uint32_t u; asm("cvt.rna.tf32.f32 %0, %1;" : "=r"(u) : "f"(v)); return u;
}

// A regs bound as (x, z, y, w): a0=(g,2t), a1=(g+8,2t), a2=(g,2t+1), a3=(g+8,2t+1)
__device__ __forceinline__ void mma8(float* c, const uint4& a,
                                     uint32_t b0, uint32_t b1) {
    asm volatile(
        "mma.sync.aligned.m16n8k8.row.col.f32.tf32.tf32.f32 "
        "{%0,%1,%2,%3}, {%4,%5,%6,%7}, {%8,%9}, {%0,%1,%2,%3};"
        : "+f"(c[0]), "+f"(c[1]), "+f"(c[2]), "+f"(c[3])
        : "r"(a.x), "r"(a.z), "r"(a.y), "r"(a.w), "r"(b0), "r"(b1));
}

// ---------------------------------------------------------------------------
// tf32 mma GEMM:  C[m,n] = sum_k A[m,k] * B[n,k]   (Kd % 64 == 0)
// Tile 128x128x32, 8 warps (2m x 4n), warp tile 64x32, double-buffered smem.
// Fetch: thread holds one row x float4 along k (LDG.128).
// Smem slot (frag, ks, L): uint4 = (row g: k2t, k2t+1 | row g+8: k2t, k2t+1),
//   addr ((frag*4+ks)*32 + (L^ks))*4 words; each thread's float4 -> 2 STS.64.
// k-permutation (hw t<->2t, t+4<->2t+1) applied to both operands (invariant).
// CVTA/CVTB: tf32-convert inputs (skip when already rounded).
// Modes: rmaxA (exp(a-rmax) on A), qcat (QK epilogue), transLd, roundOut.
// ---------------------------------------------------------------------------
template<bool CVTA, bool CVTB>
__global__ void __launch_bounds__(256, 2)
gemm_mma(const float* __restrict__ A, const float* __restrict__ Bm,
         float* __restrict__ C, int M, int Ncols, int Kd, int lda, int ldb,
         size_t sA, size_t sB, size_t sC,
         const float* __restrict__ bias, const float* __restrict__ rowscale,
         const float* __restrict__ resid, const float* __restrict__ gammaPtr,
         long long transLd, int roundOut,
         const float* __restrict__ rmaxA,
         float* __restrict__ qcat, float* __restrict__ kcat)
{
    extern __shared__ __align__(16) float smf[];
    __shared__ float srmax[128];

    const int tid  = threadIdx.x;
    const int wid  = tid >> 5;
    const int lane = tid & 31;
    const int wm   = wid >> 2;
    const int wn   = wid & 3;
    const int bz   = blockIdx.z;
    A  += (size_t)bz * sA;
    Bm += (size_t)bz * sB;
    C  += (size_t)bz * sC;
    const int m0 = blockIdx.y * 128;
    const int n0 = blockIdx.x * 128;

    const int BUFSZ = 8192;   // floats per buffer
    const int OFFB  = 4096;

    if (rmaxA && tid < 128)
        srmax[tid] = rmaxA[(size_t)bz * M + m0 + tid];

    float acc[4][4][4];
#pragma unroll
    for (int i = 0; i < 4; i++)
#pragma unroll
        for (int j = 0; j < 4; j++)
#pragma unroll
            for (int r = 0; r < 4; r++) acc[i][j][r] = 0.f;

    const int nch = Kd >> 5;
    float4 pa[4], pb[4];

    // per-thread invariants for fetch/store (t in 0..3: idx = t*256+tid)
    // r = idx>>3 (tile row), q = idx&7 (k-quad)
    const int q   = tid & 7;
    const int ks  = q >> 1;
    const int t03a = (2 * q) & 3;
    const int t03b = (2 * q + 1) & 3;

    auto FETCHA = [&](int ch) {
        const int k0 = (ch << 5) + (q << 2);
#pragma unroll
        for (int t = 0; t < 4; t++) {
            int r = (t * 256 + tid) >> 3;
            pa[t] = *(const float4*)(A + (size_t)(m0 + r) * lda + k0);
        }
    };
    auto FETCHB = [&](int ch) {
        const int k0 = (ch << 5) + (q << 2);
#pragma unroll
        for (int t = 0; t < 4; t++) {
            int r = (t * 256 + tid) >> 3;
            int ne = n0 + r;
            pb[t] = (ne < Ncols)
                  ? *(const float4*)(Bm + (size_t)ne * ldb + k0)
                  : make_float4(0.f, 0.f, 0.f, 0.f);
        }
    };

    auto STOREA = [&](int buf) {
        uint32_t* dst = (uint32_t*)(smf + buf * BUFSZ);
#pragma unroll
        for (int t = 0; t < 4; t++) {
            int r = (t * 256 + tid) >> 3;
            int fm = r >> 4, rr = r & 15;
            int g = rr & 7, half = rr >> 3;
            float4 v = pa[t];
            if (rmaxA) {
                float mx = srmax[r];
                v.x = __expf(v.x - mx); v.y = __expf(v.y - mx);
                v.z = __expf(v.z - mx); v.w = __expf(v.w - mx);
            }
            uint2 o1, o2;
            if (CVTA || rmaxA) {
                o1 = make_uint2(f2tf(v.x), f2tf(v.y));
                o2 = make_uint2(f2tf(v.z), f2tf(v.w));
            } else {
                o1 = make_uint2(__float_as_uint(v.x), __float_as_uint(v.y));
                o2 = make_uint2(__float_as_uint(v.z), __float_as_uint(v.w));
            }
            int base = (fm * 4 + ks) * 32;
            *(uint2*)(dst + (base + ((g * 4 + t03a) ^ ks)) * 4 + half * 2) = o1;
            *(uint2*)(dst + (base + ((g * 4 + t03b) ^ ks)) * 4 + half * 2) = o2;
        }
    };
    auto STOREB = [&](int buf) {
        uint32_t* dst = (uint32_t*)(smf + buf * BUFSZ + OFFB);
#pragma unroll
        for (int t = 0; t < 4; t++) {
            int r = (t * 256 + tid) >> 3;
            int fnp = r >> 4, rr = r & 15;
            int g = rr & 7, half = rr >> 3;
            float4 v = pb[t];
            uint2 o1, o2;
            if (CVTB) {
                o1 = make_uint2(f2tf(v.x), f2tf(v.y));
                o2 = make_uint2(f2tf(v.z), f2tf(v.w));
            } else {
                o1 = make_uint2(__float_as_uint(v.x), __float_as_uint(v.y));
                o2 = make_uint2(__float_as_uint(v.z), __float_as_uint(v.w));
            }
            int base = (fnp * 4 + ks) * 32;
            *(uint2*)(dst + (base + ((g * 4 + t03a) ^ ks)) * 4 + half * 2) = o1;
            *(uint2*)(dst + (base + ((g * 4 + t03b) ^ ks)) * 4 + half * 2) = o2;
        }
    };

    // B slot uint4 = (ng:b0, ng:b1, ng+8:b0, ng+8:b1)
    auto COMPUTE = [&](int buf, int ks0, int ks1) {
        const uint32_t* base = (const uint32_t*)(smf + buf * BUFSZ);
#pragma unroll
        for (int kss = ks0; kss < ks1; kss++) {
            const int lsw = lane ^ kss;
            uint4 ah[4], bh[2];
#pragma unroll
            for (int i = 0; i < 4; i++)
                ah[i] = *(const uint4*)(base + (((wm * 4 + i) * 4 + kss) * 32 + lsw) * 4);
#pragma unroll
            for (int p = 0; p < 2; p++)
                bh[p] = *(const uint4*)(base + OFFB + (((wn * 2 + p) * 4 + kss) * 32 + lsw) * 4);
#pragma unroll
            for (int i = 0; i < 4; i++)
#pragma unroll
                for (int f = 0; f < 4; f++) {
                    const uint4& B4 = bh[f >> 1];
                    uint32_t b0 = (f & 1) ? B4.z : B4.x;
                    uint32_t b1 = (f & 1) ? B4.w : B4.y;
                    mma8(acc[i][f], ah[i], b0, b1);
                }
        }
    };

    __syncthreads();                 // srmax visible
    FETCHA(0); STOREA(0);
    FETCHB(0); STOREB(0);
    __syncthreads();

    // nch is even for every launch (Kd % 64 == 0)
    for (int i = 0; i < nch; i += 2) {
        // compute buf0 (chunk i), fill buf1 (chunk i+1)
        FETCHA(i + 1);
        COMPUTE(0, 0, 2);
        STOREA(1); FETCHB(i + 1);
        COMPUTE(0, 2, 4);
        STOREB(1);
        __syncthreads();
        // compute buf1 (chunk i+1), fill buf0 (chunk i+2, unless done)
        bool have = (i + 2) < nch;
        if (have) FETCHA(i + 2);
        COMPUTE(1, 0, 2);
        if (have) { STOREA(0); FETCHB(i + 2); }
        COMPUTE(1, 2, 4);
        if (have) STOREB(0);
        __syncthreads();
    }

    // ---- epilogue: stage in smem (pitch 132), fused coalesced write ---------
    float* stage = smf;
    const int g4 = lane >> 2, t4 = lane & 3;
#pragma unroll
    for (int i = 0; i < 4; i++) {
#pragma unroll
        for (int f = 0; f < 4; f++) {
            int ml = wm * 64 + i * 16 + g4;
            int nl = wn * 32 + f * 8 + t4 * 2;
            *(float2*)&stage[ml * 132 + nl]       = make_float2(acc[i][f][0], acc[i][f][1]);
            *(float2*)&stage[(ml + 8) * 132 + nl] = make_float2(acc[i][f][2], acc[i][f][3]);
        }
    }
    __syncthreads();

    if (qcat) {
#pragma unroll 4
        for (int t = 0; t < 64; t++) {
            int idx = t * 256 + tid;
            int nn = idx & 127, mm = idx >> 7;
            int n = n0 + nn, m = m0 + mm;
            if (n < Ncols) {
                float vb = stage[mm * 132 + nn] + __ldg(bias + n);
                float hi = __uint_as_float(f2tf(vb));
                float lo = __uint_as_float(f2tf(vb - hi));
                if (n < Kk) {
                    C[(size_t)m * Kk + n] = vb;                 // segmap
                    qcat[(size_t)m * QCW + n]       = hi;
                    qcat[(size_t)m * QCW + 160 + n] = hi;
                    qcat[(size_t)m * QCW + 320 + n] = lo;
                } else {
                    int nk = n - Kk;
                    kcat[(size_t)m * QCW + nk]       = hi;
                    kcat[(size_t)m * QCW + 160 + nk] = lo;
                    kcat[(size_t)m * QCW + 320 + nk] = hi;
                }
            }
        }
        return;
    }

    const float gm = gammaPtr ? *gammaPtr : 0.f;
#pragma unroll 4
    for (int t = 0; t < 64; t++) {
        int idx = t * 256 + tid;
        int mm, nn;
        if (transLd) { mm = idx & 127; nn = idx >> 7; }
        else         { nn = idx & 127; mm = idx >> 7; }
        int n = n0 + nn, m = m0 + mm;
        if (n < Ncols) {
            float v = stage[mm * 132 + nn];
            if (bias)     v += __ldg(bias + n);
            if (rowscale) v *= rowscale[(size_t)bz * M + m];
            if (roundOut) v = __uint_as_float(f2tf(v));
            if (resid)    v = gm * v + resid[(size_t)m * Ncols + n];
            if (transLd)  C[(size_t)n * transLd + m] = v;
            else          C[(size_t)m * Ncols + n]   = v;
        }
    }
}

// ---------------------------------------------------------------------------
// Prep kernels
// ---------------------------------------------------------------------------
__global__ void split_x_kernel(const float* __restrict__ x,
                               float* __restrict__ xcat)
{
    int idx = blockIdx.x * 256 + threadIdx.x;
    if (idx >= MROWS * Cc) return;
    int row = idx >> 9, col = idx & 511;
    float v = x[idx];
    float hi = __uint_as_float(f2tf(v));
    float lo = __uint_as_float(f2tf(v - hi));
    size_t b = (size_t)row * 1536 + col;
    xcat[b] = hi; xcat[b + 512] = hi; xcat[b + 1024] = lo;
}

__global__ void prep_w_kernel(const float* __restrict__ Wq,
                              const float* __restrict__ Wk,
                              const float* __restrict__ bq,
                              const float* __restrict__ bk,
                              float* __restrict__ wcat,
                              float* __restrict__ bqk)
{
    int idx = blockIdx.x * 256 + threadIdx.x;
    if (idx < 300 * 512) {
        int r = idx >> 9, c = idx & 511;
        float v = (r < Kk) ? Wq[r * 512 + c] : Wk[(r - Kk) * 512 + c];
        float hi = __uint_as_float(f2tf(v));
        float lo = __uint_as_float(f2tf(v - hi));
        size_t b = (size_t)r * 1536 + c;
        wcat[b] = hi; wcat[b + 512] = lo; wcat[b + 1024] = hi;
    }
    if (idx < 300) bqk[idx] = (idx < Kk) ? bq[idx] : bk[idx - Kk];
}

// zero pad columns of qcat/kcat: {150..159, 310..319, 470..511} per row
__global__ void zero_pads_kernel(float* __restrict__ qcat,
                                 float* __restrict__ kcat)
{
    int row = blockIdx.x;
    int t = threadIdx.x;
    int col;
    if      (t < 10) col = 150 + t;
    else if (t < 20) col = 310 + (t - 10);
    else if (t < 62) col = 470 + (t - 20);
    else return;
    qcat[(size_t)row * QCW + col] = 0.f;
    kcat[(size_t)row * QCW + col] = 0.f;
}

// ---------------------------------------------------------------------------
// Row stats: max and 1/sum(exp(v - max)) per row of S (no write-back).
// ---------------------------------------------------------------------------
__global__ __launch_bounds__(256)
void rowstat_kernel(const float* __restrict__ S,
                    float* __restrict__ rmax, float* __restrict__ rinv)
{
    const size_t row = blockIdx.x;
    const float* p = S + row * (size_t)Nn;
    const int tid = threadIdx.x;

    float v[16];
    float mx = -3.4e38f;
#pragma unroll
    for (int i = 0; i < 16; i++) {
        v[i] = p[tid + i * 256];
        mx = fmaxf(mx, v[i]);
    }
    __shared__ float red[256];
    red[tid] = mx;
    __syncthreads();
    for (int s = 128; s > 0; s >>= 1) {
        if (tid < s) red[tid] = fmaxf(red[tid], red[tid + s]);
        __syncthreads();
    }
    mx = red[0];
    __syncthreads();

    float sum = 0.f;
#pragma unroll
    for (int i = 0; i < 16; i++) sum += __expf(v[i] - mx);
    red[tid] = sum;
    __syncthreads();
    for (int s = 128; s > 0; s >>= 1) {
        if (tid < s) red[tid] += red[tid + s];
        __syncthreads();
    }
    if (tid == 0) { rmax[row] = mx; rinv[row] = 1.f / red[0]; }
}

// ---------------------------------------------------------------------------
#define SMEM_SZ (128*132*4)   // 67584 B >= 2 k-buffers (65536 B)

extern "C" void kernel_launch(void* const* d_in, const int* in_sizes, int n_in,
                              void* d_out, int out_size)
{
    (void)in_sizes; (void)n_in; (void)out_size;
    const float* x     = (const float*)d_in[0];
    const float* Wq    = (const float*)d_in[1];
    const float* bq    = (const float*)d_in[2];
    const float* Wk    = (const float*)d_in[3];
    const float* bk    = (const float*)d_in[4];
    const float* Wv    = (const float*)d_in[5];
    const float* bv    = (const float*)d_in[6];
    const float* Wres  = (const float*)d_in[7];
    const float* bres  = (const float*)d_in[8];
    const float* gamma = (const float*)d_in[9];

    float* out     = (float*)d_out;
    float* segmap  = out;                          // (B,N,K)
    float* featmap = out + (size_t)Bb * Nn * Kk;   // (B,N,C)

    float *pXcat, *pWcat, *pbqk, *pQcat, *pKcat, *pVt, *pS, *pO, *pRmax, *pRinv;
    cudaGetSymbolAddress((void**)&pXcat, g_Xcat);
    cudaGetSymbolAddress((void**)&pWcat, g_Wcat);
    cudaGetSymbolAddress((void**)&pbqk,  g_bqk);
    cudaGetSymbolAddress((void**)&pQcat, g_Qcat);
    cudaGetSymbolAddress((void**)&pKcat, g_Kcat);
    cudaGetSymbolAddress((void**)&pVt,   g_Vt);
    cudaGetSymbolAddress((void**)&pS,    g_S);
    cudaGetSymbolAddress((void**)&pO,    g_O);
    cudaGetSymbolAddress((void**)&pRmax, g_Rmax);
    cudaGetSymbolAddress((void**)&pRinv, g_Rinv);

    cudaFuncSetAttribute(gemm_mma<true,true>,
        cudaFuncAttributeMaxDynamicSharedMemorySize, SMEM_SZ);
    cudaFuncSetAttribute(gemm_mma<false,false>,
        cudaFuncAttributeMaxDynamicSharedMemorySize, SMEM_SZ);
    cudaFuncSetAttribute(gemm_mma<true,false>,
        cudaFuncAttributeMaxDynamicSharedMemorySize, SMEM_SZ);
    cudaFuncSetAttribute(gemm_mma<false,true>,
        cudaFuncAttributeMaxDynamicSharedMemorySize, SMEM_SZ);

    // --- prep: split x / weights, zero cat-pads -----------------------------
    split_x_kernel<<<(MROWS * Cc + 255) / 256, 256>>>(x, pXcat);
    prep_w_kernel<<<(300 * 512 + 255) / 256, 256>>>(Wq, Wk, bq, bk, pWcat, pbqk);
    zero_pads_kernel<<<MROWS, 64>>>(pQcat, pKcat);

    // --- v = x @ Wv^T + bv, stored transposed (C, B*N), tf32-rounded --------
    gemm_mma<true,true><<<dim3(4, 256, 1), 256, SMEM_SZ>>>(
        x, Wv, pVt, MROWS, Cc, Cc, Cc, Cc, 0, 0, 0,
        bv, nullptr, nullptr, nullptr, (long long)MROWS, 1,
        nullptr, nullptr, nullptr);

    // --- Q,K projections (exact 3xTF32 via cat-K), inputs pre-rounded -------
    gemm_mma<false,false><<<dim3(3, 256, 1), 256, SMEM_SZ>>>(
        pXcat, pWcat, segmap, MROWS, 300, 1536, 1536, 1536, 0, 0, 0,
        pbqk, nullptr, nullptr, nullptr, 0, 0,
        nullptr, pQcat, pKcat);

    // --- S = Qcat @ Kcat^T per batch (Kd=512, padded), no cvt ----------------
    gemm_mma<false,false><<<dim3(32, 32, Bb), 256, SMEM_SZ>>>(
        pQcat, pKcat, pS, Nn, Nn, QCW, QCW, QCW,
        (size_t)Nn * QCW, (size_t)Nn * QCW, (size_t)Nn * Nn,
        nullptr, nullptr, nullptr, nullptr, 0, 0,
        nullptr, nullptr, nullptr);

    // --- row max / inverse softmax sum ---------------------------------------
    rowstat_kernel<<<MROWS, 256>>>(pS, pRmax, pRinv);

    // --- O = softmax(S) @ V; exp on the fly; Vt pre-rounded; O rounded -------
    gemm_mma<true,false><<<dim3(4, 32, Bb), 256, SMEM_SZ>>>(
        pS, pVt, pO, Nn, Cc, Nn, Nn, MROWS,
        (size_t)Nn * Nn, (size_t)Nn, (size_t)Nn * Cc,
        nullptr, pRinv, nullptr, nullptr, 0, 1,
        pRmax, nullptr, nullptr);

    // --- feat_map = gamma * (O @ Wres^T + bres) + x; O pre-rounded -----------
    gemm_mma<false,true><<<dim3(4, 256, 1), 256, SMEM_SZ>>>(
        pO, Wres, featmap, MROWS, Cc, Cc, Cc, Cc, 0, 0, 0,
        bres, nullptr, x, gamma, 0, 0,
        nullptr, nullptr, nullptr);
}

// round 12
// speedup vs baseline: 1.0055x; 1.0055x over previous
#include <cuda_runtime.h>
#include <cstdint>
#include <math.h>

#define Bb 8
#define Nn 4096
#define Cc 512
#define Kk 150
#define MROWS (Bb*Nn)
#define QCW 512          // qcat/kcat row width (3 x 160 + pad to 512)

// ---------------- scratch (device globals; no allocation allowed) -----------
__device__ float g_Xcat[(size_t)MROWS*1536]; // [x_hi | x_hi | x_lo] (tf32)
__device__ float g_Wcat[(size_t)300*1536];   // Wq,Wk rows; [hi|lo|hi] (tf32)
__device__ float g_bqk [512];
__device__ float g_Qcat[(size_t)MROWS*QCW];  // [hi|hi|lo] (tf32)
__device__ float g_Kcat[(size_t)MROWS*QCW];  // [hi|lo|hi] (tf32)
__device__ float g_Vt  [(size_t)Cc*MROWS];   // v^T (512, 32768), tf32-rounded
__device__ float g_S   [(size_t)Bb*Nn*Nn];   // raw scores fp32
__device__ float g_O   [(size_t)Bb*Nn*Cc];   // attn out, tf32-rounded
__device__ float g_Rmax[(size_t)MROWS];
__device__ float g_Rinv[(size_t)MROWS];

// ---------------- helpers ----------------------------------------------------
__device__ __forceinline__ uint32_t f2tf(float v) {
    uint32_t u; asm("cvt.rna.tf32.f32 %0, %1;" : "=r"(u) : "f"(v)); return u;
}

// A regs bound as (x, z, y, w): a0=(g,2t), a1=(g+8,2t), a2=(g,2t+1), a3=(g+8,2t+1)
__device__ __forceinline__ void mma8(float* c, const uint4& a,
                                     uint32_t b0, uint32_t b1) {
    asm volatile(
        "mma.sync.aligned.m16n8k8.row.col.f32.tf32.tf32.f32 "
        "{%0,%1,%2,%3}, {%4,%5,%6,%7}, {%8,%9}, {%0,%1,%2,%3};"
        : "+f"(c[0]), "+f"(c[1]), "+f"(c[2]), "+f"(c[3])
        : "r"(a.x), "r"(a.z), "r"(a.y), "r"(a.w), "r"(b0), "r"(b1));
}

// ---------------------------------------------------------------------------
// tf32 mma GEMM:  C[m,n] = sum_k A[m,k] * B[n,k]   (Kd % 64 == 0)
// Tile 128x128x32, 8 warps (2m x 4n), warp tile 64x32, double-buffered smem.
// Fetch: thread holds one row x float4 along k (LDG.128).
// Smem slot (frag, ks, L): uint4 = (row g: k2t, k2t+1 | row g+8: k2t, k2t+1),
//   addr ((frag*4+ks)*32 + (L^ks))*4 words; each thread's float4 -> 2 STS.64.
// k-permutation (hw t<->2t, t+4<->2t+1) applied to both operands (invariant).
// CVTA/CVTB: tf32-convert inputs (skip when already rounded).
// Modes: rmaxA (exp(a-rmax) on A), qcat (QK epilogue), transLd, roundOut.
// ---------------------------------------------------------------------------
template<bool CVTA, bool CVTB>
__global__ void __launch_bounds__(256, 2)
gemm_mma(const float* __restrict__ A, const float* __restrict__ Bm,
         float* __restrict__ C, int M, int Ncols, int Kd, int lda, int ldb,
         size_t sA, size_t sB, size_t sC,
         const float* __restrict__ bias, const float* __restrict__ rowscale,
         const float* __restrict__ resid, const float* __restrict__ gammaPtr,
         long long transLd, int roundOut,
         const float* __restrict__ rmaxA,
         float* __restrict__ qcat, float* __restrict__ kcat)
{
    extern __shared__ __align__(16) float smf[];
    __shared__ float srmax[128];

    const int tid  = threadIdx.x;
    const int wid  = tid >> 5;
    const int lane = tid & 31;
    const int wm   = wid >> 2;
    const int wn   = wid & 3;
    const int bz   = blockIdx.z;
    A  += (size_t)bz * sA;
    Bm += (size_t)bz * sB;
    C  += (size_t)bz * sC;
    const int m0 = blockIdx.y * 128;
    const int n0 = blockIdx.x * 128;

    const int BUFSZ = 8192;   // floats per buffer
    const int OFFB  = 4096;

    if (rmaxA && tid < 128)
        srmax[tid] = rmaxA[(size_t)bz * M + m0 + tid];

    float acc[4][4][4];
#pragma unroll
    for (int i = 0; i < 4; i++)
#pragma unroll
        for (int j = 0; j < 4; j++)
#pragma unroll
            for (int r = 0; r < 4; r++) acc[i][j][r] = 0.f;

    const int nch = Kd >> 5;
    float4 pa[4], pb[4];

    // per-thread invariants for fetch/store (t in 0..3: idx = t*256+tid)
    // r = idx>>3 (tile row), q = idx&7 (k-quad)
    const int q   = tid & 7;
    const int ks  = q >> 1;
    const int t03a = (2 * q) & 3;
    const int t03b = (2 * q + 1) & 3;

    auto FETCHA = [&](int ch) {
        const int k0 = (ch << 5) + (q << 2);
#pragma unroll
        for (int t = 0; t < 4; t++) {
            int r = (t * 256 + tid) >> 3;
            pa[t] = *(const float4*)(A + (size_t)(m0 + r) * lda + k0);
        }
    };
    auto FETCHB = [&](int ch) {
        const int k0 = (ch << 5) + (q << 2);
#pragma unroll
        for (int t = 0; t < 4; t++) {
            int r = (t * 256 + tid) >> 3;
            int ne = n0 + r;
            pb[t] = (ne < Ncols)
                  ? *(const float4*)(Bm + (size_t)ne * ldb + k0)
                  : make_float4(0.f, 0.f, 0.f, 0.f);
        }
    };

    auto STOREA = [&](int buf) {
        uint32_t* dst = (uint32_t*)(smf + buf * BUFSZ);
#pragma unroll
        for (int t = 0; t < 4; t++) {
            int r = (t * 256 + tid) >> 3;
            int fm = r >> 4, rr = r & 15;
            int g = rr & 7, half = rr >> 3;
            float4 v = pa[t];
            if (rmaxA) {
                float mx = srmax[r];
                v.x = __expf(v.x - mx); v.y = __expf(v.y - mx);
                v.z = __expf(v.z - mx); v.w = __expf(v.w - mx);
            }
            uint2 o1, o2;
            if (CVTA || rmaxA) {
                o1 = make_uint2(f2tf(v.x), f2tf(v.y));
                o2 = make_uint2(f2tf(v.z), f2tf(v.w));
            } else {
                o1 = make_uint2(__float_as_uint(v.x), __float_as_uint(v.y));
                o2 = make_uint2(__float_as_uint(v.z), __float_as_uint(v.w));
            }
            int base = (fm * 4 + ks) * 32;
            *(uint2*)(dst + (base + ((g * 4 + t03a) ^ ks)) * 4 + half * 2) = o1;
            *(uint2*)(dst + (base + ((g * 4 + t03b) ^ ks)) * 4 + half * 2) = o2;
        }
    };
    auto STOREB = [&](int buf) {
        uint32_t* dst = (uint32_t*)(smf + buf * BUFSZ + OFFB);
#pragma unroll
        for (int t = 0; t < 4; t++) {
            int r = (t * 256 + tid) >> 3;
            int fnp = r >> 4, rr = r & 15;
            int g = rr & 7, half = rr >> 3;
            float4 v = pb[t];
            uint2 o1, o2;
            if (CVTB) {
                o1 = make_uint2(f2tf(v.x), f2tf(v.y));
                o2 = make_uint2(f2tf(v.z), f2tf(v.w));
            } else {
                o1 = make_uint2(__float_as_uint(v.x), __float_as_uint(v.y));
                o2 = make_uint2(__float_as_uint(v.z), __float_as_uint(v.w));
            }
            int base = (fnp * 4 + ks) * 32;
            *(uint2*)(dst + (base + ((g * 4 + t03a) ^ ks)) * 4 + half * 2) = o1;
            *(uint2*)(dst + (base + ((g * 4 + t03b) ^ ks)) * 4 + half * 2) = o2;
        }
    };

    // B slot uint4 = (ng:b0, ng:b1, ng+8:b0, ng+8:b1)
    auto COMPUTE = [&](int buf, int ks0, int ks1) {
        const uint32_t* base = (const uint32_t*)(smf + buf * BUFSZ);
#pragma unroll
        for (int kss = ks0; kss < ks1; kss++) {
            const int lsw = lane ^ kss;
            uint4 ah[4], bh[2];
#pragma unroll
            for (int i = 0; i < 4; i++)
                ah[i] = *(const uint4*)(base + (((wm * 4 + i) * 4 + kss) * 32 + lsw) * 4);
#pragma unroll
            for (int p = 0; p < 2; p++)
                bh[p] = *(const uint4*)(base + OFFB + (((wn * 2 + p) * 4 + kss) * 32 + lsw) * 4);
#pragma unroll
            for (int i = 0; i < 4; i++)
#pragma unroll
                for (int f = 0; f < 4; f++) {
                    const uint4& B4 = bh[f >> 1];
                    uint32_t b0 = (f & 1) ? B4.z : B4.x;
                    uint32_t b1 = (f & 1) ? B4.w : B4.y;
                    mma8(acc[i][f], ah[i], b0, b1);
                }
        }
    };

    __syncthreads();                 // srmax visible
    FETCHA(0); STOREA(0);
    FETCHB(0); STOREB(0);
    __syncthreads();

    // nch is even for every launch (Kd % 64 == 0)
    for (int i = 0; i < nch; i += 2) {
        // compute buf0 (chunk i), fill buf1 (chunk i+1)
        FETCHA(i + 1);
        COMPUTE(0, 0, 2);
        STOREA(1); FETCHB(i + 1);
        COMPUTE(0, 2, 4);
        STOREB(1);
        __syncthreads();
        // compute buf1 (chunk i+1), fill buf0 (chunk i+2, unless done)
        bool have = (i + 2) < nch;
        if (have) FETCHA(i + 2);
        COMPUTE(1, 0, 2);
        if (have) { STOREA(0); FETCHB(i + 2); }
        COMPUTE(1, 2, 4);
        if (have) STOREB(0);
        __syncthreads();
    }

    // ---- epilogue: stage in smem (pitch 132), fused coalesced write ---------
    float* stage = smf;
    const int g4 = lane >> 2, t4 = lane & 3;
#pragma unroll
    for (int i = 0; i < 4; i++) {
#pragma unroll
        for (int f = 0; f < 4; f++) {
            int ml = wm * 64 + i * 16 + g4;
            int nl = wn * 32 + f * 8 + t4 * 2;
            *(float2*)&stage[ml * 132 + nl]       = make_float2(acc[i][f][0], acc[i][f][1]);
            *(float2*)&stage[(ml + 8) * 132 + nl] = make_float2(acc[i][f][2], acc[i][f][3]);
        }
    }
    __syncthreads();

    if (qcat) {
#pragma unroll 4
        for (int t = 0; t < 64; t++) {
            int idx = t * 256 + tid;
            int nn = idx & 127, mm = idx >> 7;
            int n = n0 + nn, m = m0 + mm;
            if (n < Ncols) {
                float vb = stage[mm * 132 + nn] + __ldg(bias + n);
                float hi = __uint_as_float(f2tf(vb));
                float lo = __uint_as_float(f2tf(vb - hi));
                if (n < Kk) {
                    C[(size_t)m * Kk + n] = vb;                 // segmap
                    qcat[(size_t)m * QCW + n]       = hi;
                    qcat[(size_t)m * QCW + 160 + n] = hi;
                    qcat[(size_t)m * QCW + 320 + n] = lo;
                } else {
                    int nk = n - Kk;
                    kcat[(size_t)m * QCW + nk]       = hi;
                    kcat[(size_t)m * QCW + 160 + nk] = lo;
                    kcat[(size_t)m * QCW + 320 + nk] = hi;
                }
            }
        }
        return;
    }

    const float gm = gammaPtr ? *gammaPtr : 0.f;
#pragma unroll 4
    for (int t = 0; t < 64; t++) {
        int idx = t * 256 + tid;
        int mm, nn;
        if (transLd) { mm = idx & 127; nn = idx >> 7; }
        else         { nn = idx & 127; mm = idx >> 7; }
        int n = n0 + nn, m = m0 + mm;
        if (n < Ncols) {
            float v = stage[mm * 132 + nn];
            if (bias)     v += __ldg(bias + n);
            if (rowscale) v *= rowscale[(size_t)bz * M + m];
            if (roundOut) v = __uint_as_float(f2tf(v));
            if (resid)    v = gm * v + resid[(size_t)m * Ncols + n];
            if (transLd)  C[(size_t)n * transLd + m] = v;
            else          C[(size_t)m * Ncols + n]   = v;
        }
    }
}

// ---------------------------------------------------------------------------
// Prep kernels
// ---------------------------------------------------------------------------
__global__ void split_x_kernel(const float* __restrict__ x,
                               float* __restrict__ xcat)
{
    int idx = blockIdx.x * 256 + threadIdx.x;
    if (idx >= MROWS * Cc) return;
    int row = idx >> 9, col = idx & 511;
    float v = x[idx];
    float hi = __uint_as_float(f2tf(v));
    float lo = __uint_as_float(f2tf(v - hi));
    size_t b = (size_t)row * 1536 + col;
    xcat[b] = hi; xcat[b + 512] = hi; xcat[b + 1024] = lo;
}

__global__ void prep_w_kernel(const float* __restrict__ Wq,
                              const float* __restrict__ Wk,
                              const float* __restrict__ bq,
                              const float* __restrict__ bk,
                              float* __restrict__ wcat,
                              float* __restrict__ bqk)
{
    int idx = blockIdx.x * 256 + threadIdx.x;
    if (idx < 300 * 512) {
        int r = idx >> 9, c = idx & 511;
        float v = (r < Kk) ? Wq[r * 512 + c] : Wk[(r - Kk) * 512 + c];
        float hi = __uint_as_float(f2tf(v));
        float lo = __uint_as_float(f2tf(v - hi));
        size_t b = (size_t)r * 1536 + c;
        wcat[b] = hi; wcat[b + 512] = lo; wcat[b + 1024] = hi;
    }
    if (idx < 300) bqk[idx] = (idx < Kk) ? bq[idx] : bk[idx - Kk];
}

// zero pad columns of qcat/kcat: {150..159, 310..319, 470..511} per row
__global__ void zero_pads_kernel(float* __restrict__ qcat,
                                 float* __restrict__ kcat)
{
    int row = blockIdx.x;
    int t = threadIdx.x;
    int col;
    if      (t < 10) col = 150 + t;
    else if (t < 20) col = 310 + (t - 10);
    else if (t < 62) col = 470 + (t - 20);
    else return;
    qcat[(size_t)row * QCW + col] = 0.f;
    kcat[(size_t)row * QCW + col] = 0.f;
}

// ---------------------------------------------------------------------------
// Row stats: max and 1/sum(exp(v - max)) per row of S (no write-back).
// ---------------------------------------------------------------------------
__global__ __launch_bounds__(256)
void rowstat_kernel(const float* __restrict__ S,
                    float* __restrict__ rmax, float* __restrict__ rinv)
{
    const size_t row = blockIdx.x;
    const float* p = S + row * (size_t)Nn;
    const int tid = threadIdx.x;

    float v[16];
    float mx = -3.4e38f;
#pragma unroll
    for (int i = 0; i < 16; i++) {
        v[i] = p[tid + i * 256];
        mx = fmaxf(mx, v[i]);
    }
    __shared__ float red[256];
    red[tid] = mx;
    __syncthreads();
    for (int s = 128; s > 0; s >>= 1) {
        if (tid < s) red[tid] = fmaxf(red[tid], red[tid + s]);
        __syncthreads();
    }
    mx = red[0];
    __syncthreads();

    float sum = 0.f;
#pragma unroll
    for (int i = 0; i < 16; i++) sum += __expf(v[i] - mx);
    red[tid] = sum;
    __syncthreads();
    for (int s = 128; s > 0; s >>= 1) {
        if (tid < s) red[tid] += red[tid + s];
        __syncthreads();
    }
    if (tid == 0) { rmax[row] = mx; rinv[row] = 1.f / red[0]; }
}

// ---------------------------------------------------------------------------
#define SMEM_SZ (128*132*4)   // 67584 B >= 2 k-buffers (65536 B)

extern "C" void kernel_launch(void* const* d_in, const int* in_sizes, int n_in,
                              void* d_out, int out_size)
{
    (void)in_sizes; (void)n_in; (void)out_size;
    const float* x     = (const float*)d_in[0];
    const float* Wq    = (const float*)d_in[1];
    const float* bq    = (const float*)d_in[2];
    const float* Wk    = (const float*)d_in[3];
    const float* bk    = (const float*)d_in[4];
    const float* Wv    = (const float*)d_in[5];
    const float* bv    = (const float*)d_in[6];
    const float* Wres  = (const float*)d_in[7];
    const float* bres  = (const float*)d_in[8];
    const float* gamma = (const float*)d_in[9];

    float* out     = (float*)d_out;
    float* segmap  = out;                          // (B,N,K)
    float* featmap = out + (size_t)Bb * Nn * Kk;   // (B,N,C)

    float *pXcat, *pWcat, *pbqk, *pQcat, *pKcat, *pVt, *pS, *pO, *pRmax, *pRinv;
    cudaGetSymbolAddress((void**)&pXcat, g_Xcat);
    cudaGetSymbolAddress((void**)&pWcat, g_Wcat);
    cudaGetSymbolAddress((void**)&pbqk,  g_bqk);
    cudaGetSymbolAddress((void**)&pQcat, g_Qcat);
    cudaGetSymbolAddress((void**)&pKcat, g_Kcat);
    cudaGetSymbolAddress((void**)&pVt,   g_Vt);
    cudaGetSymbolAddress((void**)&pS,    g_S);
    cudaGetSymbolAddress((void**)&pO,    g_O);
    cudaGetSymbolAddress((void**)&pRmax, g_Rmax);
    cudaGetSymbolAddress((void**)&pRinv, g_Rinv);

    cudaFuncSetAttribute(gemm_mma<true,true>,
        cudaFuncAttributeMaxDynamicSharedMemorySize, SMEM_SZ);
    cudaFuncSetAttribute(gemm_mma<false,false>,
        cudaFuncAttributeMaxDynamicSharedMemorySize, SMEM_SZ);
    cudaFuncSetAttribute(gemm_mma<true,false>,
        cudaFuncAttributeMaxDynamicSharedMemorySize, SMEM_SZ);
    cudaFuncSetAttribute(gemm_mma<false,true>,
        cudaFuncAttributeMaxDynamicSharedMemorySize, SMEM_SZ);

    // --- prep: split x / weights, zero cat-pads -----------------------------
    split_x_kernel<<<(MROWS * Cc + 255) / 256, 256>>>(x, pXcat);
    prep_w_kernel<<<(300 * 512 + 255) / 256, 256>>>(Wq, Wk, bq, bk, pWcat, pbqk);
    zero_pads_kernel<<<MROWS, 64>>>(pQcat, pKcat);

    // --- v = x @ Wv^T + bv, stored transposed (C, B*N), tf32-rounded --------
    gemm_mma<true,true><<<dim3(4, 256, 1), 256, SMEM_SZ>>>(
        x, Wv, pVt, MROWS, Cc, Cc, Cc, Cc, 0, 0, 0,
        bv, nullptr, nullptr, nullptr, (long long)MROWS, 1,
        nullptr, nullptr, nullptr);

    // --- Q,K projections (exact 3xTF32 via cat-K), inputs pre-rounded -------
    gemm_mma<false,false><<<dim3(3, 256, 1), 256, SMEM_SZ>>>(
        pXcat, pWcat, segmap, MROWS, 300, 1536, 1536, 1536, 0, 0, 0,
        pbqk, nullptr, nullptr, nullptr, 0, 0,
        nullptr, pQcat, pKcat);

    // --- S = Qcat @ Kcat^T per batch (Kd=512, padded), no cvt ----------------
    gemm_mma<false,false><<<dim3(32, 32, Bb), 256, SMEM_SZ>>>(
        pQcat, pKcat, pS, Nn, Nn, QCW, QCW, QCW,
        (size_t)Nn * QCW, (size_t)Nn * QCW, (size_t)Nn * Nn,
        nullptr, nullptr, nullptr, nullptr, 0, 0,
        nullptr, nullptr, nullptr);

    // --- row max / inverse softmax sum ---------------------------------------
    rowstat_kernel<<<MROWS, 256>>>(pS, pRmax, pRinv);

    // --- O = softmax(S) @ V; exp on the fly; Vt pre-rounded; O rounded -------
    gemm_mma<true,false><<<dim3(4, 32, Bb), 256, SMEM_SZ>>>(
        pS, pVt, pO, Nn, Cc, Nn, Nn, MROWS,
        (size_t)Nn * Nn, (size_t)Nn, (size_t)Nn * Cc,
        nullptr, pRinv, nullptr, nullptr, 0, 1,
        pRmax, nullptr, nullptr);

    // --- feat_map = gamma * (O @ Wres^T + bres) + x; O pre-rounded -----------
    gemm_mma<false,true><<<dim3(4, 256, 1), 256, SMEM_SZ>>>(
        pO, Wres, featmap, MROWS, Cc, Cc, Cc, Cc, 0, 0, 0,
        bres, nullptr, x, gamma, 0, 0,
        nullptr, nullptr, nullptr);
}